// round 4
// baseline (speedup 1.0000x reference)
#include <cuda_runtime.h>
#include <cstdint>

#define B_  4
#define S_  1024
#define E_  1024
#define H_  16
#define HD_ 64
#define N3E 3072
#define LDS_PAD 36   // floats per smem row (BK=32 + 4 pad)

// ---------------- scratch ----------------
__device__ float g_Q [(size_t)B_ * H_ * S_ * HD_];
__device__ float g_K [(size_t)B_ * H_ * S_ * HD_];
__device__ float g_V [(size_t)B_ * H_ * S_ * HD_];
__device__ float g_Vt[(size_t)B_ * H_ * S_ * HD_];   // [g][d][s]
__device__ float g_O [(size_t)B_ * S_ * E_];
__device__ int   g_mask_kind;

// ---------------- helpers ----------------
__device__ __forceinline__ uint32_t smem_u32(const void* p) {
    uint32_t a;
    asm("{ .reg .u64 t; cvta.to.shared.u64 t, %1; cvt.u32.u64 %0, t; }"
        : "=r"(a) : "l"(p));
    return a;
}
__device__ __forceinline__ uint32_t cvt_tf32(float x) {
    uint32_t u; asm("cvt.rna.tf32.f32 %0, %1;" : "=r"(u) : "f"(x)); return u;
}
__device__ __forceinline__ void ldsm4(uint32_t* r, uint32_t addr) {
    asm volatile("ldmatrix.sync.aligned.m8n8.x4.shared.b16 {%0,%1,%2,%3}, [%4];"
                 : "=r"(r[0]), "=r"(r[1]), "=r"(r[2]), "=r"(r[3]) : "r"(addr));
}
__device__ __forceinline__ void mma8(float* c, const uint32_t* a, const uint32_t* b) {
    asm volatile(
        "mma.sync.aligned.m16n8k8.row.col.f32.tf32.tf32.f32 "
        "{%0,%1,%2,%3}, {%4,%5,%6,%7}, {%8,%9}, {%0,%1,%2,%3};"
        : "+f"(c[0]), "+f"(c[1]), "+f"(c[2]), "+f"(c[3])
        : "r"(a[0]), "r"(a[1]), "r"(a[2]), "r"(a[3]), "r"(b[0]), "r"(b[1]));
}

// ---------------- generic mainloop (qkv / out GEMMs) ----------------
template<int BN, int WM, int WN>
__device__ __forceinline__ void gemm_mainloop(
    const float* __restrict__ A, int lda,
    const float* __restrict__ Bm, int ldb, int K,
    float* sA, float* sB, float* acc)
{
    constexpr int MT = 128 / (WM * 16);
    constexpr int NT = BN / (WN * 8);
    const int tid = threadIdx.x;
    const int warp = tid >> 5, lane = tid & 31;
    const int wm = warp % WM, wn = warp / WM;
    const int m0 = wm * MT * 16;
    const int n0 = wn * NT * 8;

    const uint32_t sa_base = smem_u32(sA);
    const uint32_t sb_base = smem_u32(sB);

    const int a_row = (lane & 7) + ((lane & 8) ? 8 : 0);
    const int a_k   = (lane & 16) ? 4 : 0;
    const int b_row = (lane & 7) + ((lane & 16) ? 8 : 0);
    const int b_k   = (lane & 8) ? 4 : 0;

    const int nch = K >> 5;
    for (int kc = 0; kc < nch; kc++) {
#pragma unroll
        for (int i = 0; i < (128 * 8) / 256; i++) {
            int f = tid + i * 256;
            int r = f >> 3, q = f & 7;
            float4 v = *reinterpret_cast<const float4*>(
                &A[(size_t)r * lda + (kc << 5) + (q << 2)]);
            uint4 u;
            u.x = cvt_tf32(v.x); u.y = cvt_tf32(v.y);
            u.z = cvt_tf32(v.z); u.w = cvt_tf32(v.w);
            *reinterpret_cast<uint4*>(&sA[r * LDS_PAD + (q << 2)]) = u;
        }
#pragma unroll
        for (int i = 0; i < (BN * 8) / 256; i++) {
            int f = tid + i * 256;
            int r = f >> 3, q = f & 7;
            float4 v = *reinterpret_cast<const float4*>(
                &Bm[(size_t)r * ldb + (kc << 5) + (q << 2)]);
            uint4 u;
            u.x = cvt_tf32(v.x); u.y = cvt_tf32(v.y);
            u.z = cvt_tf32(v.z); u.w = cvt_tf32(v.w);
            *reinterpret_cast<uint4*>(&sB[r * LDS_PAD + (q << 2)]) = u;
        }
        __syncthreads();

#pragma unroll
        for (int ks = 0; ks < 4; ks++) {
            const int kk = ks << 3;
            uint32_t afr[MT][4];
#pragma unroll
            for (int mt = 0; mt < MT; mt++) {
                uint32_t addr = sa_base +
                    (uint32_t)(((m0 + mt * 16 + a_row) * LDS_PAD + kk + a_k) << 2);
                ldsm4(afr[mt], addr);
            }
            uint32_t bfr[NT][2];
#pragma unroll
            for (int np = 0; np < NT / 2; np++) {
                uint32_t r[4];
                uint32_t addr = sb_base +
                    (uint32_t)(((n0 + np * 16 + b_row) * LDS_PAD + kk + b_k) << 2);
                ldsm4(r, addr);
                bfr[np * 2 + 0][0] = r[0]; bfr[np * 2 + 0][1] = r[1];
                bfr[np * 2 + 1][0] = r[2]; bfr[np * 2 + 1][1] = r[3];
            }
#pragma unroll
            for (int mt = 0; mt < MT; mt++)
#pragma unroll
                for (int nt = 0; nt < NT; nt++)
                    mma8(&acc[(mt * NT + nt) * 4], afr[mt], bfr[nt]);
        }
        __syncthreads();
    }
}

// ---------------- mask dtype detection ----------------
__global__ void detect_mask_kind_kernel(const unsigned int* __restrict__ mw) {
    if (threadIdx.x == 0 && blockIdx.x == 0) {
        int kind = 0;
        for (int i = 0; i < 256; i++) {
            unsigned int w = mw[i];
            if (w == 0x3F800000u) { kind = 2; break; }
            if (w > 1u) kind = 1;
        }
        g_mask_kind = kind;
    }
}

// ---------------- kernel 1: QKV = X @ W^T + b, scatter Q/K/V ----------------
__global__ __launch_bounds__(256, 2)
void qkv_mma_kernel(const float* __restrict__ X, const float* __restrict__ W,
                    const float* __restrict__ bias) {
    constexpr int BN = 128, WM = 2, WN = 4;
    constexpr int MT = 4, NT = 4;
    __shared__ float sA[128 * LDS_PAD];
    __shared__ float sB[BN * LDS_PAD];
    float acc[MT * NT * 4];
#pragma unroll
    for (int i = 0; i < MT * NT * 4; i++) acc[i] = 0.f;

    const int row0 = blockIdx.y * 128;
    const int col0 = blockIdx.x * 128;
    gemm_mainloop<BN, WM, WN>(X + (size_t)row0 * E_, E_,
                              W + (size_t)col0 * E_, E_, E_, sA, sB, acc);

    const int tid = threadIdx.x;
    const int warp = tid >> 5, lane = tid & 31;
    const int wm = warp % WM, wn = warp / WM;

#pragma unroll
    for (int mt = 0; mt < MT; mt++) {
#pragma unroll
        for (int nt = 0; nt < NT; nt++) {
            const float* c = &acc[(mt * NT + nt) * 4];
            int n = col0 + wn * 32 + nt * 8 + 2 * (lane & 3);
            int h = n / 192;
            int rr = n - h * 192;
            int part = rr >> 6;
            int d = rr & 63;
            float* dst = (part == 0) ? g_Q : ((part == 1) ? g_K : g_V);
            float b0 = bias[n], b1 = bias[n + 1];
#pragma unroll
            for (int half = 0; half < 2; half++) {
                int m = row0 + wm * 64 + mt * 16 + (lane >> 2) + half * 8;
                int bidx = m >> 10;
                int s = m & 1023;
                float2 v = make_float2(c[half * 2 + 0] + b0, c[half * 2 + 1] + b1);
                *reinterpret_cast<float2*>(
                    &dst[(((size_t)bidx * H_ + h) * S_ + s) * HD_ + d]) = v;
            }
        }
    }
}

// ---------------- V transpose ----------------
__global__ void vt_kernel() {
    __shared__ float t[32][33];
    int g = blockIdx.z;
    int s0 = blockIdx.y * 32, d0 = blockIdx.x * 32;
    const float* V = g_V + (size_t)g * S_ * HD_;
    float* Vt = g_Vt + (size_t)g * HD_ * S_;
    for (int i = threadIdx.y; i < 32; i += 8)
        t[i][threadIdx.x] = V[(size_t)(s0 + i) * HD_ + d0 + threadIdx.x];
    __syncthreads();
    for (int i = threadIdx.y; i < 32; i += 8)
        Vt[(size_t)(d0 + i) * S_ + s0 + threadIdx.x] = t[threadIdx.x][i];
}

// ---------------- flash attention: fused scores + softmax + PV ----------------
// grid (8 rowblocks, 64 g), 256 threads, dynamic smem.
// smem layout (floats): sQ[128*68] | sSK[128*132] (K tile stride 68 / P tile stride 132)
//                       | sV[64*132] | sMax[128*4] | sSum[128*4]
#define FQ_OFF  0
#define FS_OFF  8704
#define FV_OFF  25600
#define FMX_OFF 34048
#define FSM_OFF 34560
#define FLASH_SMEM_BYTES ((34560 + 512) * 4)

__global__ __launch_bounds__(256, 1)
void flash_kernel(const float* __restrict__ prev, const void* __restrict__ mask) {
    extern __shared__ float sm[];
    float* sQ   = sm + FQ_OFF;
    float* sSK  = sm + FS_OFF;
    float* sV   = sm + FV_OFF;
    float* sMax = sm + FMX_OFF;
    float* sSum = sm + FSM_OFF;

    const int g = blockIdx.y;
    const int row0 = blockIdx.x * 128;
    const int tid = threadIdx.x, warp = tid >> 5, lane = tid & 31;
    const int wm = warp & 1, wn = warp >> 1;
    const int m0 = wm * 64;          // warp rows [m0, m0+64)
    const int nS0 = wn * 32;         // S warp cols
    const int nO0 = wn * 16;         // O warp cols (d)
    const int rowq = lane >> 2;
    const int coln2 = 2 * (lane & 3);

    const int a_row = (lane & 7) + ((lane & 8) ? 8 : 0);
    const int a_k   = (lane & 16) ? 4 : 0;
    const int b_row = (lane & 7) + ((lane & 16) ? 8 : 0);
    const int b_k   = (lane & 8) ? 4 : 0;

    const float* Qg  = g_Q  + (size_t)g * S_ * HD_ + (size_t)row0 * HD_;
    const float* Kg  = g_K  + (size_t)g * S_ * HD_;
    const float* Vtg = g_Vt + (size_t)g * HD_ * S_;

    // load Q tile (tf32-rounded), stride 68
#pragma unroll
    for (int i = 0; i < 8; i++) {
        int f = tid + i * 256;
        int r = f >> 4, q = f & 15;
        float4 v = *reinterpret_cast<const float4*>(&Qg[(size_t)r * HD_ + (q << 2)]);
        uint4 u;
        u.x = cvt_tf32(v.x); u.y = cvt_tf32(v.y);
        u.z = cvt_tf32(v.z); u.w = cvt_tf32(v.w);
        *reinterpret_cast<uint4*>(&sQ[r * 68 + (q << 2)]) = u;
    }

    float o_acc[4][2][4];
#pragma unroll
    for (int a = 0; a < 4; a++)
#pragma unroll
        for (int b = 0; b < 2; b++)
#pragma unroll
            for (int cidx = 0; cidx < 4; cidx++) o_acc[a][b][cidx] = 0.f;
    float m_i[4][2], l_i[4][2];
#pragma unroll
    for (int a = 0; a < 4; a++) { m_i[a][0] = m_i[a][1] = -1e30f; l_i[a][0] = l_i[a][1] = 0.f; }

    const uint32_t sq_b = smem_u32(sQ);
    const uint32_t ss_b = smem_u32(sSK);
    const uint32_t sv_b = smem_u32(sV);

    const int kind = g_mask_kind;
    const int* mi = (const int*)mask;
    const unsigned char* mb = (const unsigned char*)mask;
    const float* mf = (const float*)mask;

    for (int cblk = 0; cblk < 8; cblk++) {
        const int col0 = cblk * 128;
        // ---- load K tile (stride 68, in sSK) + Vt tile (stride 132) ----
#pragma unroll
        for (int i = 0; i < 8; i++) {
            int f = tid + i * 256;
            int r = f >> 4, q = f & 15;
            float4 v = *reinterpret_cast<const float4*>(
                &Kg[(size_t)(col0 + r) * HD_ + (q << 2)]);
            uint4 u;
            u.x = cvt_tf32(v.x); u.y = cvt_tf32(v.y);
            u.z = cvt_tf32(v.z); u.w = cvt_tf32(v.w);
            *reinterpret_cast<uint4*>(&sSK[r * 68 + (q << 2)]) = u;
        }
#pragma unroll
        for (int i = 0; i < 8; i++) {
            int f = tid + i * 256;
            int r = f >> 5, q = f & 31;
            float4 v = *reinterpret_cast<const float4*>(
                &Vtg[(size_t)r * S_ + col0 + (q << 2)]);
            uint4 u;
            u.x = cvt_tf32(v.x); u.y = cvt_tf32(v.y);
            u.z = cvt_tf32(v.z); u.w = cvt_tf32(v.w);
            *reinterpret_cast<uint4*>(&sV[r * 132 + (q << 2)]) = u;
        }
        __syncthreads();

        // ---- S = Q @ K^T (K=64: 8 ksteps) ----
        float s_acc[4][4][4];
#pragma unroll
        for (int a = 0; a < 4; a++)
#pragma unroll
            for (int b = 0; b < 4; b++)
#pragma unroll
                for (int cidx = 0; cidx < 4; cidx++) s_acc[a][b][cidx] = 0.f;

#pragma unroll
        for (int ks = 0; ks < 8; ks++) {
            const int kk = ks << 3;
            uint32_t afr[4][4];
#pragma unroll
            for (int mt = 0; mt < 4; mt++)
                ldsm4(afr[mt], sq_b + (uint32_t)(((m0 + mt * 16 + a_row) * 68 + kk + a_k) << 2));
            uint32_t bfr[4][2];
#pragma unroll
            for (int np = 0; np < 2; np++) {
                uint32_t r[4];
                ldsm4(r, ss_b + (uint32_t)(((nS0 + np * 16 + b_row) * 68 + kk + b_k) << 2));
                bfr[np * 2 + 0][0] = r[0]; bfr[np * 2 + 0][1] = r[1];
                bfr[np * 2 + 1][0] = r[2]; bfr[np * 2 + 1][1] = r[3];
            }
#pragma unroll
            for (int mt = 0; mt < 4; mt++)
#pragma unroll
                for (int nt = 0; nt < 4; nt++)
                    mma8(s_acc[mt][nt], afr[mt], bfr[nt]);
        }

        // ---- s = S/32 + prev, masked -> -1e30; per-warp row max ----
        float rmax[4][2];
#pragma unroll
        for (int mt = 0; mt < 4; mt++) { rmax[mt][0] = -1e30f; rmax[mt][1] = -1e30f; }

#pragma unroll
        for (int mt = 0; mt < 4; mt++) {
#pragma unroll
            for (int nt = 0; nt < 4; nt++) {
                int n = col0 + nS0 + nt * 8 + coln2;
#pragma unroll
                for (int half = 0; half < 2; half++) {
                    int m = row0 + m0 + mt * 16 + rowq + half * 8;
                    size_t pidx = ((size_t)g * S_ + m) * S_ + n;
                    size_t midx = (size_t)m * S_ + n;
                    float2 pv = *reinterpret_cast<const float2*>(&prev[pidx]);
                    bool k0, k1;
                    if (kind == 0)      { k0 = mi[midx] != 0;   k1 = mi[midx + 1] != 0; }
                    else if (kind == 1) { k0 = mb[midx] != 0;   k1 = mb[midx + 1] != 0; }
                    else                { k0 = mf[midx] != 0.f; k1 = mf[midx + 1] != 0.f; }
                    float v0 = k0 ? -1e30f : fmaf(s_acc[mt][nt][half * 2 + 0], 0.03125f, pv.x);
                    float v1 = k1 ? -1e30f : fmaf(s_acc[mt][nt][half * 2 + 1], 0.03125f, pv.y);
                    s_acc[mt][nt][half * 2 + 0] = v0;
                    s_acc[mt][nt][half * 2 + 1] = v1;
                    rmax[mt][half] = fmaxf(rmax[mt][half], fmaxf(v0, v1));
                }
            }
#pragma unroll
            for (int half = 0; half < 2; half++) {
                float r = rmax[mt][half];
                r = fmaxf(r, __shfl_xor_sync(0xffffffffu, r, 1));
                r = fmaxf(r, __shfl_xor_sync(0xffffffffu, r, 2));
                rmax[mt][half] = r;
                if ((lane & 3) == 0)
                    sMax[(m0 + mt * 16 + rowq + half * 8) * 4 + wn] = r;
            }
        }
        __syncthreads();   // max partials ready; also: all K-tile reads done

        // ---- m_new, alpha, rescale O; p = exp(s-m), write to sSK (stride 132); sums ----
        float mnew[4][2];
#pragma unroll
        for (int mt = 0; mt < 4; mt++) {
#pragma unroll
            for (int half = 0; half < 2; half++) {
                int rl = m0 + mt * 16 + rowq + half * 8;
                float mc = fmaxf(fmaxf(sMax[rl * 4 + 0], sMax[rl * 4 + 1]),
                                 fmaxf(sMax[rl * 4 + 2], sMax[rl * 4 + 3]));
                float mo = m_i[mt][half];
                float mn = fmaxf(mo, mc);
                float alpha = __expf(mo - mn);
                m_i[mt][half] = mn;
                mnew[mt][half] = mn;
                l_i[mt][half] *= alpha;
#pragma unroll
                for (int nt = 0; nt < 2; nt++) {
                    o_acc[mt][nt][half * 2 + 0] *= alpha;
                    o_acc[mt][nt][half * 2 + 1] *= alpha;
                }
            }
        }

        float rsum[4][2];
#pragma unroll
        for (int mt = 0; mt < 4; mt++) { rsum[mt][0] = 0.f; rsum[mt][1] = 0.f; }

#pragma unroll
        for (int mt = 0; mt < 4; mt++) {
#pragma unroll
            for (int nt = 0; nt < 4; nt++) {
#pragma unroll
                for (int half = 0; half < 2; half++) {
                    float p0 = __expf(s_acc[mt][nt][half * 2 + 0] - mnew[mt][half]);
                    float p1 = __expf(s_acc[mt][nt][half * 2 + 1] - mnew[mt][half]);
                    rsum[mt][half] += p0 + p1;
                    uint2 u = make_uint2(cvt_tf32(p0), cvt_tf32(p1));
                    int rl = m0 + mt * 16 + rowq + half * 8;
                    *reinterpret_cast<uint2*>(
                        &sSK[rl * 132 + nS0 + nt * 8 + coln2]) = u;
                }
            }
#pragma unroll
            for (int half = 0; half < 2; half++) {
                float r = rsum[mt][half];
                r += __shfl_xor_sync(0xffffffffu, r, 1);
                r += __shfl_xor_sync(0xffffffffu, r, 2);
                if ((lane & 3) == 0)
                    sSum[(m0 + mt * 16 + rowq + half * 8) * 4 + wn] = r;
            }
        }
        __syncthreads();   // P tile + sum partials ready

#pragma unroll
        for (int mt = 0; mt < 4; mt++)
#pragma unroll
            for (int half = 0; half < 2; half++) {
                int rl = m0 + mt * 16 + rowq + half * 8;
                l_i[mt][half] += sSum[rl * 4 + 0] + sSum[rl * 4 + 1]
                               + sSum[rl * 4 + 2] + sSum[rl * 4 + 3];
            }

        // ---- O += P @ Vt^T (K=128: 16 ksteps) ----
#pragma unroll
        for (int ks = 0; ks < 16; ks++) {
            const int kk = ks << 3;
            uint32_t afr[4][4];
#pragma unroll
            for (int mt = 0; mt < 4; mt++)
                ldsm4(afr[mt], ss_b + (uint32_t)(((m0 + mt * 16 + a_row) * 132 + kk + a_k) << 2));
            uint32_t r[4];
            ldsm4(r, sv_b + (uint32_t)(((nO0 + b_row) * 132 + kk + b_k) << 2));
            uint32_t bfr[2][2];
            bfr[0][0] = r[0]; bfr[0][1] = r[1];
            bfr[1][0] = r[2]; bfr[1][1] = r[3];
#pragma unroll
            for (int mt = 0; mt < 4; mt++)
#pragma unroll
                for (int nt = 0; nt < 2; nt++)
                    mma8(o_acc[mt][nt], afr[mt], bfr[nt]);
        }
        __syncthreads();   // P/V tiles consumed; safe to overwrite next iter
    }

    // ---- epilogue: O /= l, store to g_O [b][s][h*64+d] ----
    const int bidx = g >> 4;
    const int h = g & 15;
#pragma unroll
    for (int mt = 0; mt < 4; mt++) {
#pragma unroll
        for (int half = 0; half < 2; half++) {
            float inv = 1.f / l_i[mt][half];
            int s = row0 + m0 + mt * 16 + rowq + half * 8;
#pragma unroll
            for (int nt = 0; nt < 2; nt++) {
                int d = nO0 + nt * 8 + coln2;
                float2 v = make_float2(o_acc[mt][nt][half * 2 + 0] * inv,
                                       o_acc[mt][nt][half * 2 + 1] * inv);
                *reinterpret_cast<float2*>(
                    &g_O[((size_t)bidx * S_ + s) * E_ + h * HD_ + d]) = v;
            }
        }
    }
}

// ---------------- kernel 4: out = O @ o_w^T + o_b ----------------
__global__ __launch_bounds__(256, 2)
void out_mma_kernel(const float* __restrict__ W, const float* __restrict__ bias,
                    float* __restrict__ out) {
    constexpr int BN = 128, WM = 2, WN = 4;
    constexpr int MT = 4, NT = 4;
    __shared__ float sA[128 * LDS_PAD];
    __shared__ float sB[BN * LDS_PAD];
    float acc[MT * NT * 4];
#pragma unroll
    for (int i = 0; i < MT * NT * 4; i++) acc[i] = 0.f;

    const int row0 = blockIdx.y * 128;
    const int col0 = blockIdx.x * 128;
    gemm_mainloop<BN, WM, WN>(g_O + (size_t)row0 * E_, E_,
                              W + (size_t)col0 * E_, E_, E_, sA, sB, acc);

    const int tid = threadIdx.x;
    const int warp = tid >> 5, lane = tid & 31;
    const int wm = warp % WM, wn = warp / WM;

#pragma unroll
    for (int mt = 0; mt < MT; mt++) {
#pragma unroll
        for (int nt = 0; nt < NT; nt++) {
            const float* c = &acc[(mt * NT + nt) * 4];
            int n = col0 + wn * 32 + nt * 8 + 2 * (lane & 3);
            float b0 = bias[n], b1 = bias[n + 1];
#pragma unroll
            for (int half = 0; half < 2; half++) {
                int m = row0 + wm * 64 + mt * 16 + (lane >> 2) + half * 8;
                float2 v = make_float2(c[half * 2 + 0] + b0, c[half * 2 + 1] + b1);
                *reinterpret_cast<float2*>(&out[(size_t)m * E_ + n]) = v;
            }
        }
    }
}

// ---------------- launch ----------------
extern "C" void kernel_launch(void* const* d_in, const int* in_sizes, int n_in,
                              void* d_out, int out_size) {
    const float* x     = (const float*)d_in[0];
    const void*  mask  = d_in[1];
    const float* prev  = (const float*)d_in[2];
    const float* qkv_w = (const float*)d_in[3];
    const float* qkv_b = (const float*)d_in[4];
    const float* o_w   = (const float*)d_in[5];
    const float* o_b   = (const float*)d_in[6];
    float* out = (float*)d_out;

    cudaFuncSetAttribute(flash_kernel,
                         cudaFuncAttributeMaxDynamicSharedMemorySize,
                         FLASH_SMEM_BYTES);

    detect_mask_kind_kernel<<<1, 32>>>((const unsigned int*)mask);

    qkv_mma_kernel<<<dim3(N3E / 128, (B_ * S_) / 128), 256>>>(x, qkv_w, qkv_b);

    vt_kernel<<<dim3(HD_ / 32, S_ / 32, B_ * H_), dim3(32, 8)>>>();

    flash_kernel<<<dim3(S_ / 128, B_ * H_), 256, FLASH_SMEM_BYTES>>>(prev, mask);

    out_mma_kernel<<<dim3(E_ / 128, (B_ * S_) / 128), 256>>>(o_w, o_b, out);
}

// round 5
// speedup vs baseline: 1.6950x; 1.6950x over previous
#include <cuda_runtime.h>
#include <cstdint>

#define B_  4
#define S_  1024
#define E_  1024
#define H_  16
#define HD_ 64
#define N3E 3072
#define LDS_PAD 36

// ---------------- scratch ----------------
__device__ float g_Q [(size_t)B_ * H_ * S_ * HD_];
__device__ float g_K [(size_t)B_ * H_ * S_ * HD_];
__device__ float g_V [(size_t)B_ * H_ * S_ * HD_];
__device__ float g_Vt[(size_t)B_ * H_ * S_ * HD_];   // [g][d][s]
__device__ float g_O [(size_t)B_ * S_ * E_];
__device__ float g_maskF[(size_t)S_ * S_];           // 0 or -1e30
__device__ int   g_mask_kind;

// ---------------- helpers ----------------
__device__ __forceinline__ uint32_t smem_u32(const void* p) {
    uint32_t a;
    asm("{ .reg .u64 t; cvta.to.shared.u64 t, %1; cvt.u32.u64 %0, t; }"
        : "=r"(a) : "l"(p));
    return a;
}
__device__ __forceinline__ uint32_t cvt_tf32(float x) {
    uint32_t u; asm("cvt.rna.tf32.f32 %0, %1;" : "=r"(u) : "f"(x)); return u;
}
__device__ __forceinline__ void ldsm4(uint32_t* r, uint32_t addr) {
    asm volatile("ldmatrix.sync.aligned.m8n8.x4.shared.b16 {%0,%1,%2,%3}, [%4];"
                 : "=r"(r[0]), "=r"(r[1]), "=r"(r[2]), "=r"(r[3]) : "r"(addr));
}
__device__ __forceinline__ void mma8(float* c, const uint32_t* a, const uint32_t* b) {
    asm volatile(
        "mma.sync.aligned.m16n8k8.row.col.f32.tf32.tf32.f32 "
        "{%0,%1,%2,%3}, {%4,%5,%6,%7}, {%8,%9}, {%0,%1,%2,%3};"
        : "+f"(c[0]), "+f"(c[1]), "+f"(c[2]), "+f"(c[3])
        : "r"(a[0]), "r"(a[1]), "r"(a[2]), "r"(a[3]), "r"(b[0]), "r"(b[1]));
}

// ---------------- generic mainloop (qkv / out GEMMs) ----------------
template<int BN, int WM, int WN>
__device__ __forceinline__ void gemm_mainloop(
    const float* __restrict__ A, int lda,
    const float* __restrict__ Bm, int ldb, int K,
    float* sA, float* sB, float* acc)
{
    constexpr int MT = 128 / (WM * 16);
    constexpr int NT = BN / (WN * 8);
    const int tid = threadIdx.x;
    const int warp = tid >> 5, lane = tid & 31;
    const int wm = warp % WM, wn = warp / WM;
    const int m0 = wm * MT * 16;
    const int n0 = wn * NT * 8;

    const uint32_t sa_base = smem_u32(sA);
    const uint32_t sb_base = smem_u32(sB);

    const int a_row = (lane & 7) + ((lane & 8) ? 8 : 0);
    const int a_k   = (lane & 16) ? 4 : 0;
    const int b_row = (lane & 7) + ((lane & 16) ? 8 : 0);
    const int b_k   = (lane & 8) ? 4 : 0;

    const int nch = K >> 5;
    for (int kc = 0; kc < nch; kc++) {
#pragma unroll
        for (int i = 0; i < (128 * 8) / 256; i++) {
            int f = tid + i * 256;
            int r = f >> 3, q = f & 7;
            float4 v = *reinterpret_cast<const float4*>(
                &A[(size_t)r * lda + (kc << 5) + (q << 2)]);
            uint4 u;
            u.x = cvt_tf32(v.x); u.y = cvt_tf32(v.y);
            u.z = cvt_tf32(v.z); u.w = cvt_tf32(v.w);
            *reinterpret_cast<uint4*>(&sA[r * LDS_PAD + (q << 2)]) = u;
        }
#pragma unroll
        for (int i = 0; i < (BN * 8) / 256; i++) {
            int f = tid + i * 256;
            int r = f >> 3, q = f & 7;
            float4 v = *reinterpret_cast<const float4*>(
                &Bm[(size_t)r * ldb + (kc << 5) + (q << 2)]);
            uint4 u;
            u.x = cvt_tf32(v.x); u.y = cvt_tf32(v.y);
            u.z = cvt_tf32(v.z); u.w = cvt_tf32(v.w);
            *reinterpret_cast<uint4*>(&sB[r * LDS_PAD + (q << 2)]) = u;
        }
        __syncthreads();

#pragma unroll
        for (int ks = 0; ks < 4; ks++) {
            const int kk = ks << 3;
            uint32_t afr[MT][4];
#pragma unroll
            for (int mt = 0; mt < MT; mt++) {
                uint32_t addr = sa_base +
                    (uint32_t)(((m0 + mt * 16 + a_row) * LDS_PAD + kk + a_k) << 2);
                ldsm4(afr[mt], addr);
            }
            uint32_t bfr[NT][2];
#pragma unroll
            for (int np = 0; np < NT / 2; np++) {
                uint32_t r[4];
                uint32_t addr = sb_base +
                    (uint32_t)(((n0 + np * 16 + b_row) * LDS_PAD + kk + b_k) << 2);
                ldsm4(r, addr);
                bfr[np * 2 + 0][0] = r[0]; bfr[np * 2 + 0][1] = r[1];
                bfr[np * 2 + 1][0] = r[2]; bfr[np * 2 + 1][1] = r[3];
            }
#pragma unroll
            for (int mt = 0; mt < MT; mt++)
#pragma unroll
                for (int nt = 0; nt < NT; nt++)
                    mma8(&acc[(mt * NT + nt) * 4], afr[mt], bfr[nt]);
        }
        __syncthreads();
    }
}

// ---------------- mask handling ----------------
__global__ void detect_mask_kind_kernel(const unsigned int* __restrict__ mw) {
    if (threadIdx.x == 0 && blockIdx.x == 0) {
        int kind = 0;
        for (int i = 0; i < 256; i++) {
            unsigned int w = mw[i];
            if (w == 0x3F800000u) { kind = 2; break; }
            if (w > 1u) kind = 1;
        }
        g_mask_kind = kind;
    }
}

__global__ __launch_bounds__(256)
void mask_to_float_kernel(const void* __restrict__ mask) {
    int idx = blockIdx.x * 256 + threadIdx.x;
    int kind = g_mask_kind;
    bool m;
    if (kind == 0)      m = ((const int*)mask)[idx] != 0;
    else if (kind == 1) m = ((const unsigned char*)mask)[idx] != 0;
    else                m = ((const float*)mask)[idx] != 0.f;
    g_maskF[idx] = m ? -1e30f : 0.f;
}

// ---------------- kernel 1: QKV = X @ W^T + b, scatter Q/K/V ----------------
__global__ __launch_bounds__(256, 2)
void qkv_mma_kernel(const float* __restrict__ X, const float* __restrict__ W,
                    const float* __restrict__ bias) {
    constexpr int BN = 128, WM = 2, WN = 4;
    constexpr int MT = 4, NT = 4;
    __shared__ float sA[128 * LDS_PAD];
    __shared__ float sB[BN * LDS_PAD];
    float acc[MT * NT * 4];
#pragma unroll
    for (int i = 0; i < MT * NT * 4; i++) acc[i] = 0.f;

    const int row0 = blockIdx.y * 128;
    const int col0 = blockIdx.x * 128;
    gemm_mainloop<BN, WM, WN>(X + (size_t)row0 * E_, E_,
                              W + (size_t)col0 * E_, E_, E_, sA, sB, acc);

    const int tid = threadIdx.x;
    const int warp = tid >> 5, lane = tid & 31;
    const int wm = warp % WM, wn = warp / WM;

#pragma unroll
    for (int mt = 0; mt < MT; mt++) {
#pragma unroll
        for (int nt = 0; nt < NT; nt++) {
            const float* c = &acc[(mt * NT + nt) * 4];
            int n = col0 + wn * 32 + nt * 8 + 2 * (lane & 3);
            int h = n / 192;
            int rr = n - h * 192;
            int part = rr >> 6;
            int d = rr & 63;
            float* dst = (part == 0) ? g_Q : ((part == 1) ? g_K : g_V);
            float b0 = bias[n], b1 = bias[n + 1];
#pragma unroll
            for (int half = 0; half < 2; half++) {
                int m = row0 + wm * 64 + mt * 16 + (lane >> 2) + half * 8;
                int bidx = m >> 10;
                int s = m & 1023;
                float2 v = make_float2(c[half * 2 + 0] + b0, c[half * 2 + 1] + b1);
                *reinterpret_cast<float2*>(
                    &dst[(((size_t)bidx * H_ + h) * S_ + s) * HD_ + d]) = v;
            }
        }
    }
}

// ---------------- V transpose ----------------
__global__ void vt_kernel() {
    __shared__ float t[32][33];
    int g = blockIdx.z;
    int s0 = blockIdx.y * 32, d0 = blockIdx.x * 32;
    const float* V = g_V + (size_t)g * S_ * HD_;
    float* Vt = g_Vt + (size_t)g * HD_ * S_;
    for (int i = threadIdx.y; i < 32; i += 8)
        t[i][threadIdx.x] = V[(size_t)(s0 + i) * HD_ + d0 + threadIdx.x];
    __syncthreads();
    for (int i = threadIdx.y; i < 32; i += 8)
        Vt[(size_t)(d0 + i) * S_ + s0 + threadIdx.x] = t[threadIdx.x][i];
}

// ---------------- flash attention, 64-row CTAs, 2 CTAs/SM ----------------
// smem (floats): sQ[64*68]=4352 | sSK: K[128*68]=8704 / P[64*132]=8448 (aliased)
//                | sV[64*132]=8448 | sMax[64*4] | sSum[64*4]
#define FQ_OFF  0
#define FS_OFF  4352
#define FV_OFF  13056
#define FMX_OFF 21504
#define FSM_OFF 21760
#define FLASH_SMEM_BYTES (22016 * 4)

__global__ __launch_bounds__(256, 2)
void flash_kernel(const float* __restrict__ prev) {
    extern __shared__ float sm[];
    float* sQ   = sm + FQ_OFF;
    float* sSK  = sm + FS_OFF;
    float* sV   = sm + FV_OFF;
    float* sMax = sm + FMX_OFF;
    float* sSum = sm + FSM_OFF;

    const int g = blockIdx.y;
    const int row0 = blockIdx.x * 64;
    const int tid = threadIdx.x, warp = tid >> 5, lane = tid & 31;
    const int wm = warp & 1, wn = warp >> 1;
    const int m0 = wm * 32;          // warp rows [m0, m0+32)
    const int nS0 = wn * 32;         // S warp cols
    const int nO0 = wn * 16;         // O warp cols
    const int rowq = lane >> 2;
    const int coln2 = 2 * (lane & 3);

    const int a_row = (lane & 7) + ((lane & 8) ? 8 : 0);
    const int a_k   = (lane & 16) ? 4 : 0;
    const int b_row = (lane & 7) + ((lane & 16) ? 8 : 0);
    const int b_k   = (lane & 8) ? 4 : 0;

    const float* Qg  = g_Q  + (size_t)g * S_ * HD_ + (size_t)row0 * HD_;
    const float* Kg  = g_K  + (size_t)g * S_ * HD_;
    const float* Vtg = g_Vt + (size_t)g * HD_ * S_;

    // Q tile 64x64, stride 68
#pragma unroll
    for (int i = 0; i < 4; i++) {
        int f = tid + i * 256;
        int r = f >> 4, q = f & 15;
        float4 v = *reinterpret_cast<const float4*>(&Qg[(size_t)r * HD_ + (q << 2)]);
        uint4 u;
        u.x = cvt_tf32(v.x); u.y = cvt_tf32(v.y);
        u.z = cvt_tf32(v.z); u.w = cvt_tf32(v.w);
        *reinterpret_cast<uint4*>(&sQ[r * 68 + (q << 2)]) = u;
    }

    float o_acc[2][2][4];
#pragma unroll
    for (int a = 0; a < 2; a++)
#pragma unroll
        for (int b = 0; b < 2; b++)
#pragma unroll
            for (int c = 0; c < 4; c++) o_acc[a][b][c] = 0.f;
    float m_i[2][2], l_i[2][2];
#pragma unroll
    for (int a = 0; a < 2; a++) { m_i[a][0] = m_i[a][1] = -1e30f; l_i[a][0] = l_i[a][1] = 0.f; }

    const uint32_t sq_b = smem_u32(sQ);
    const uint32_t ss_b = smem_u32(sSK);
    const uint32_t sv_b = smem_u32(sV);

    for (int cblk = 0; cblk < 8; cblk++) {
        const int col0 = cblk * 128;
        // K tile 128x64 (stride 68), Vt tile 64x128 (stride 132)
#pragma unroll
        for (int i = 0; i < 8; i++) {
            int f = tid + i * 256;
            int r = f >> 4, q = f & 15;
            float4 v = *reinterpret_cast<const float4*>(
                &Kg[(size_t)(col0 + r) * HD_ + (q << 2)]);
            uint4 u;
            u.x = cvt_tf32(v.x); u.y = cvt_tf32(v.y);
            u.z = cvt_tf32(v.z); u.w = cvt_tf32(v.w);
            *reinterpret_cast<uint4*>(&sSK[r * 68 + (q << 2)]) = u;
        }
#pragma unroll
        for (int i = 0; i < 8; i++) {
            int f = tid + i * 256;
            int r = f >> 5, q = f & 31;
            float4 v = *reinterpret_cast<const float4*>(
                &Vtg[(size_t)r * S_ + col0 + (q << 2)]);
            uint4 u;
            u.x = cvt_tf32(v.x); u.y = cvt_tf32(v.y);
            u.z = cvt_tf32(v.z); u.w = cvt_tf32(v.w);
            *reinterpret_cast<uint4*>(&sV[r * 132 + (q << 2)]) = u;
        }

        // ---- init acc with 32*(prev + maskF): loads overlap with smem stores above ----
        float s_acc[2][4][4];
#pragma unroll
        for (int mt = 0; mt < 2; mt++) {
#pragma unroll
            for (int nt = 0; nt < 4; nt++) {
                int n = col0 + nS0 + nt * 8 + coln2;
#pragma unroll
                for (int half = 0; half < 2; half++) {
                    int m = row0 + m0 + mt * 16 + rowq + half * 8;
                    float2 pv = *reinterpret_cast<const float2*>(
                        &prev[((size_t)g * S_ + m) * S_ + n]);
                    float2 mf = *reinterpret_cast<const float2*>(
                        &g_maskF[(size_t)m * S_ + n]);
                    s_acc[mt][nt][half * 2 + 0] = 32.f * (pv.x + mf.x);
                    s_acc[mt][nt][half * 2 + 1] = 32.f * (pv.y + mf.y);
                }
            }
        }
        __syncthreads();

        // ---- S += Q @ K^T (8 ksteps) ----
#pragma unroll
        for (int ks = 0; ks < 8; ks++) {
            const int kk = ks << 3;
            uint32_t afr[2][4];
#pragma unroll
            for (int mt = 0; mt < 2; mt++)
                ldsm4(afr[mt], sq_b + (uint32_t)(((m0 + mt * 16 + a_row) * 68 + kk + a_k) << 2));
            uint32_t bfr[4][2];
#pragma unroll
            for (int np = 0; np < 2; np++) {
                uint32_t r[4];
                ldsm4(r, ss_b + (uint32_t)(((nS0 + np * 16 + b_row) * 68 + kk + b_k) << 2));
                bfr[np * 2 + 0][0] = r[0]; bfr[np * 2 + 0][1] = r[1];
                bfr[np * 2 + 1][0] = r[2]; bfr[np * 2 + 1][1] = r[3];
            }
#pragma unroll
            for (int mt = 0; mt < 2; mt++)
#pragma unroll
                for (int nt = 0; nt < 4; nt++)
                    mma8(s_acc[mt][nt], afr[mt], bfr[nt]);
        }

        // ---- v = s/32 (prev+mask already inside); row max ----
        float rmax[2][2];
#pragma unroll
        for (int mt = 0; mt < 2; mt++) { rmax[mt][0] = -1e30f; rmax[mt][1] = -1e30f; }
#pragma unroll
        for (int mt = 0; mt < 2; mt++) {
#pragma unroll
            for (int nt = 0; nt < 4; nt++) {
#pragma unroll
                for (int c = 0; c < 4; c++) s_acc[mt][nt][c] *= 0.03125f;
#pragma unroll
                for (int half = 0; half < 2; half++)
                    rmax[mt][half] = fmaxf(rmax[mt][half],
                        fmaxf(s_acc[mt][nt][half * 2], s_acc[mt][nt][half * 2 + 1]));
            }
#pragma unroll
            for (int half = 0; half < 2; half++) {
                float r = rmax[mt][half];
                r = fmaxf(r, __shfl_xor_sync(0xffffffffu, r, 1));
                r = fmaxf(r, __shfl_xor_sync(0xffffffffu, r, 2));
                if ((lane & 3) == 0)
                    sMax[(m0 + mt * 16 + rowq + half * 8) * 4 + wn] = r;
            }
        }
        __syncthreads();   // K reads done + max partials visible

        // ---- online rescale; p = exp(v - mnew) -> sSK (stride 132); sums ----
        float mnew[2][2];
#pragma unroll
        for (int mt = 0; mt < 2; mt++) {
#pragma unroll
            for (int half = 0; half < 2; half++) {
                int rl = m0 + mt * 16 + rowq + half * 8;
                float mc = fmaxf(fmaxf(sMax[rl * 4 + 0], sMax[rl * 4 + 1]),
                                 fmaxf(sMax[rl * 4 + 2], sMax[rl * 4 + 3]));
                float mo = m_i[mt][half];
                float mn = fmaxf(mo, mc);
                float alpha = __expf(mo - mn);
                m_i[mt][half] = mn;
                mnew[mt][half] = mn;
                l_i[mt][half] *= alpha;
#pragma unroll
                for (int nt = 0; nt < 2; nt++) {
                    o_acc[mt][nt][half * 2 + 0] *= alpha;
                    o_acc[mt][nt][half * 2 + 1] *= alpha;
                }
            }
        }

        float rsum[2][2];
#pragma unroll
        for (int mt = 0; mt < 2; mt++) { rsum[mt][0] = 0.f; rsum[mt][1] = 0.f; }
#pragma unroll
        for (int mt = 0; mt < 2; mt++) {
#pragma unroll
            for (int nt = 0; nt < 4; nt++) {
#pragma unroll
                for (int half = 0; half < 2; half++) {
                    float p0 = __expf(s_acc[mt][nt][half * 2 + 0] - mnew[mt][half]);
                    float p1 = __expf(s_acc[mt][nt][half * 2 + 1] - mnew[mt][half]);
                    rsum[mt][half] += p0 + p1;
                    uint2 u = make_uint2(cvt_tf32(p0), cvt_tf32(p1));
                    int rl = m0 + mt * 16 + rowq + half * 8;
                    *reinterpret_cast<uint2*>(
                        &sSK[rl * 132 + nS0 + nt * 8 + coln2]) = u;
                }
            }
#pragma unroll
            for (int half = 0; half < 2; half++) {
                float r = rsum[mt][half];
                r += __shfl_xor_sync(0xffffffffu, r, 1);
                r += __shfl_xor_sync(0xffffffffu, r, 2);
                if ((lane & 3) == 0)
                    sSum[(m0 + mt * 16 + rowq + half * 8) * 4 + wn] = r;
            }
        }
        __syncthreads();   // P + sums ready

#pragma unroll
        for (int mt = 0; mt < 2; mt++)
#pragma unroll
            for (int half = 0; half < 2; half++) {
                int rl = m0 + mt * 16 + rowq + half * 8;
                l_i[mt][half] += sSum[rl * 4 + 0] + sSum[rl * 4 + 1]
                               + sSum[rl * 4 + 2] + sSum[rl * 4 + 3];
            }

        // ---- O += P @ Vt^T (16 ksteps) ----
#pragma unroll
        for (int ks = 0; ks < 16; ks++) {
            const int kk = ks << 3;
            uint32_t afr[2][4];
#pragma unroll
            for (int mt = 0; mt < 2; mt++)
                ldsm4(afr[mt], ss_b + (uint32_t)(((m0 + mt * 16 + a_row) * 132 + kk + a_k) << 2));
            uint32_t r[4];
            ldsm4(r, sv_b + (uint32_t)(((nO0 + b_row) * 132 + kk + b_k) << 2));
            uint32_t bfr[2][2];
            bfr[0][0] = r[0]; bfr[0][1] = r[1];
            bfr[1][0] = r[2]; bfr[1][1] = r[3];
#pragma unroll
            for (int mt = 0; mt < 2; mt++)
#pragma unroll
                for (int nt = 0; nt < 2; nt++)
                    mma8(o_acc[mt][nt], afr[mt], bfr[nt]);
        }
        __syncthreads();   // tiles consumed
    }

    // ---- epilogue ----
    const int bidx = g >> 4;
    const int h = g & 15;
#pragma unroll
    for (int mt = 0; mt < 2; mt++) {
#pragma unroll
        for (int half = 0; half < 2; half++) {
            float inv = 1.f / l_i[mt][half];
            int s = row0 + m0 + mt * 16 + rowq + half * 8;
#pragma unroll
            for (int nt = 0; nt < 2; nt++) {
                int d = nO0 + nt * 8 + coln2;
                float2 v = make_float2(o_acc[mt][nt][half * 2 + 0] * inv,
                                       o_acc[mt][nt][half * 2 + 1] * inv);
                *reinterpret_cast<float2*>(
                    &g_O[((size_t)bidx * S_ + s) * E_ + h * HD_ + d]) = v;
            }
        }
    }
}

// ---------------- kernel 4: out = O @ o_w^T + o_b ----------------
__global__ __launch_bounds__(256, 2)
void out_mma_kernel(const float* __restrict__ W, const float* __restrict__ bias,
                    float* __restrict__ out) {
    constexpr int BN = 128, WM = 2, WN = 4;
    constexpr int MT = 4, NT = 4;
    __shared__ float sA[128 * LDS_PAD];
    __shared__ float sB[BN * LDS_PAD];
    float acc[MT * NT * 4];
#pragma unroll
    for (int i = 0; i < MT * NT * 4; i++) acc[i] = 0.f;

    const int row0 = blockIdx.y * 128;
    const int col0 = blockIdx.x * 128;
    gemm_mainloop<BN, WM, WN>(g_O + (size_t)row0 * E_, E_,
                              W + (size_t)col0 * E_, E_, E_, sA, sB, acc);

    const int tid = threadIdx.x;
    const int warp = tid >> 5, lane = tid & 31;
    const int wm = warp % WM, wn = warp / WM;

#pragma unroll
    for (int mt = 0; mt < MT; mt++) {
#pragma unroll
        for (int nt = 0; nt < NT; nt++) {
            const float* c = &acc[(mt * NT + nt) * 4];
            int n = col0 + wn * 32 + nt * 8 + 2 * (lane & 3);
            float b0 = bias[n], b1 = bias[n + 1];
#pragma unroll
            for (int half = 0; half < 2; half++) {
                int m = row0 + wm * 64 + mt * 16 + (lane >> 2) + half * 8;
                float2 v = make_float2(c[half * 2 + 0] + b0, c[half * 2 + 1] + b1);
                *reinterpret_cast<float2*>(&out[(size_t)m * E_ + n]) = v;
            }
        }
    }
}

// ---------------- launch ----------------
extern "C" void kernel_launch(void* const* d_in, const int* in_sizes, int n_in,
                              void* d_out, int out_size) {
    const float* x     = (const float*)d_in[0];
    const void*  mask  = d_in[1];
    const float* prev  = (const float*)d_in[2];
    const float* qkv_w = (const float*)d_in[3];
    const float* qkv_b = (const float*)d_in[4];
    const float* o_w   = (const float*)d_in[5];
    const float* o_b   = (const float*)d_in[6];
    float* out = (float*)d_out;

    cudaFuncSetAttribute(flash_kernel,
                         cudaFuncAttributeMaxDynamicSharedMemorySize,
                         FLASH_SMEM_BYTES);

    detect_mask_kind_kernel<<<1, 32>>>((const unsigned int*)mask);
    mask_to_float_kernel<<<(S_ * S_) / 256, 256>>>(mask);

    qkv_mma_kernel<<<dim3(N3E / 128, (B_ * S_) / 128), 256>>>(x, qkv_w, qkv_b);

    vt_kernel<<<dim3(HD_ / 32, S_ / 32, B_ * H_), dim3(32, 8)>>>();

    flash_kernel<<<dim3(S_ / 64, B_ * H_), 256, FLASH_SMEM_BYTES>>>(prev);

    out_mma_kernel<<<dim3(E_ / 128, (B_ * S_) / 128), 256>>>(o_w, o_b, out);
}

// round 7
// speedup vs baseline: 1.7955x; 1.0593x over previous
#include <cuda_runtime.h>
#include <cstdint>

#define B_  4
#define S_  1024
#define E_  1024
#define H_  16
#define HD_ 64
#define N3E 3072
#define LDS_PAD 36

// ---------------- scratch ----------------
__device__ float g_Q [(size_t)B_ * H_ * S_ * HD_];   // tf32-rounded, pre-scaled by 1/32
__device__ float g_K [(size_t)B_ * H_ * S_ * HD_];   // tf32-rounded
__device__ float g_V [(size_t)B_ * H_ * S_ * HD_];   // tf32-rounded
__device__ float g_Vt[(size_t)B_ * H_ * S_ * HD_];   // [g][d][s], tf32-rounded
__device__ float g_O [(size_t)B_ * S_ * E_];         // tf32-rounded
__device__ float g_maskF[(size_t)S_ * S_];           // 0 or -1e30
__device__ float g_Xr [(size_t)B_ * S_ * E_];        // tf32(x)
__device__ float g_Wr [(size_t)N3E * E_];            // tf32(qkv_w)
__device__ float g_OWr[(size_t)E_ * E_];             // tf32(o_w)
__device__ int   g_mask_kind;

// ---------------- helpers ----------------
__device__ __forceinline__ uint32_t smem_u32(const void* p) {
    uint32_t a;
    asm("{ .reg .u64 t; cvta.to.shared.u64 t, %1; cvt.u32.u64 %0, t; }"
        : "=r"(a) : "l"(p));
    return a;
}
__device__ __forceinline__ uint32_t cvt_tf32(float x) {
    uint32_t u; asm("cvt.rna.tf32.f32 %0, %1;" : "=r"(u) : "f"(x)); return u;
}
__device__ __forceinline__ float round_tf32f(float x) {
    return __uint_as_float(cvt_tf32(x));
}
__device__ __forceinline__ void ldsm4(uint32_t* r, uint32_t addr) {
    asm volatile("ldmatrix.sync.aligned.m8n8.x4.shared.b16 {%0,%1,%2,%3}, [%4];"
                 : "=r"(r[0]), "=r"(r[1]), "=r"(r[2]), "=r"(r[3]) : "r"(addr));
}
__device__ __forceinline__ void mma8(float* c, const uint32_t* a, const uint32_t* b) {
    asm volatile(
        "mma.sync.aligned.m16n8k8.row.col.f32.tf32.tf32.f32 "
        "{%0,%1,%2,%3}, {%4,%5,%6,%7}, {%8,%9}, {%0,%1,%2,%3};"
        : "+f"(c[0]), "+f"(c[1]), "+f"(c[2]), "+f"(c[3])
        : "r"(a[0]), "r"(a[1]), "r"(a[2]), "r"(a[3]), "r"(b[0]), "r"(b[1]));
}
__device__ __forceinline__ void cpa16(uint32_t saddr, const void* g) {
    asm volatile("cp.async.cg.shared.global [%0], [%1], 16;"
                 :: "r"(saddr), "l"(g) : "memory");
}
__device__ __forceinline__ void cpa_commit() {
    asm volatile("cp.async.commit_group;" ::: "memory");
}
template<int N> __device__ __forceinline__ void cpa_wait() {
    asm volatile("cp.async.wait_group %0;" :: "n"(N) : "memory");
}

// ---------------- tf32 pre-round (dst resolved in DEVICE code; __device__ globals
// must never be referenced from host) ----------------
__global__ __launch_bounds__(256)
void round4_kernel(const float4* __restrict__ in, int which) {
    float4* dst = (which == 0) ? reinterpret_cast<float4*>(g_Xr)
                : (which == 1) ? reinterpret_cast<float4*>(g_Wr)
                               : reinterpret_cast<float4*>(g_OWr);
    int i = blockIdx.x * 256 + threadIdx.x;
    float4 v = in[i];
    v.x = round_tf32f(v.x); v.y = round_tf32f(v.y);
    v.z = round_tf32f(v.z); v.w = round_tf32f(v.w);
    dst[i] = v;
}

// ---------------- mask handling ----------------
__global__ void detect_mask_kind_kernel(const unsigned int* __restrict__ mw) {
    if (threadIdx.x == 0 && blockIdx.x == 0) {
        int kind = 0;
        for (int i = 0; i < 256; i++) {
            unsigned int w = mw[i];
            if (w == 0x3F800000u) { kind = 2; break; }
            if (w > 1u) kind = 1;
        }
        g_mask_kind = kind;
    }
}
__global__ __launch_bounds__(256)
void mask_to_float_kernel(const void* __restrict__ mask) {
    int idx = blockIdx.x * 256 + threadIdx.x;
    int kind = g_mask_kind;
    bool m;
    if (kind == 0)      m = ((const int*)mask)[idx] != 0;
    else if (kind == 1) m = ((const unsigned char*)mask)[idx] != 0;
    else                m = ((const float*)mask)[idx] != 0.f;
    g_maskF[idx] = m ? -1e30f : 0.f;
}

// ---------------- async double-buffered mainloop (operands pre-rounded) ----------------
template<int BN, int WM, int WN>
__device__ __forceinline__ void gemm_mainloop_async(
    const float* __restrict__ A, int lda,
    const float* __restrict__ Bm, int ldb, int K,
    float* sA, float* sB, float* acc)
{
    constexpr int MT = 128 / (WM * 16);
    constexpr int NT = BN / (WN * 8);
    constexpr uint32_t ABYTES = 128 * LDS_PAD * 4;
    constexpr uint32_t BBYTES = BN * LDS_PAD * 4;
    const int tid = threadIdx.x;
    const int warp = tid >> 5, lane = tid & 31;
    const int wm = warp % WM, wn = warp / WM;
    const int m0 = wm * MT * 16;
    const int n0 = wn * NT * 8;

    const uint32_t sa_base = smem_u32(sA);
    const uint32_t sb_base = smem_u32(sB);

    const int a_row = (lane & 7) + ((lane & 8) ? 8 : 0);
    const int a_k   = (lane & 16) ? 4 : 0;
    const int b_row = (lane & 7) + ((lane & 16) ? 8 : 0);
    const int b_k   = (lane & 8) ? 4 : 0;

    const int nch = K >> 5;

    auto issue = [&](int kc, int buf) {
#pragma unroll
        for (int i = 0; i < (128 * 8) / 256; i++) {
            int f = tid + i * 256;
            int r = f >> 3, q = f & 7;
            cpa16(sa_base + buf * ABYTES + (uint32_t)((r * LDS_PAD + (q << 2)) << 2),
                  &A[(size_t)r * lda + (kc << 5) + (q << 2)]);
        }
#pragma unroll
        for (int i = 0; i < (BN * 8) / 256; i++) {
            int f = tid + i * 256;
            int r = f >> 3, q = f & 7;
            cpa16(sb_base + buf * BBYTES + (uint32_t)((r * LDS_PAD + (q << 2)) << 2),
                  &Bm[(size_t)r * ldb + (kc << 5) + (q << 2)]);
        }
        cpa_commit();
    };

    issue(0, 0);
    for (int kc = 0; kc < nch; kc++) {
        if (kc + 1 < nch) { issue(kc + 1, (kc + 1) & 1); cpa_wait<1>(); }
        else cpa_wait<0>();
        __syncthreads();

        const uint32_t sa = sa_base + (kc & 1) * ABYTES;
        const uint32_t sb = sb_base + (kc & 1) * BBYTES;
#pragma unroll
        for (int ks = 0; ks < 4; ks++) {
            const int kk = ks << 3;
            uint32_t afr[MT][4];
#pragma unroll
            for (int mt = 0; mt < MT; mt++)
                ldsm4(afr[mt], sa + (uint32_t)(((m0 + mt * 16 + a_row) * LDS_PAD + kk + a_k) << 2));
            uint32_t bfr[NT][2];
#pragma unroll
            for (int np = 0; np < NT / 2; np++) {
                uint32_t r[4];
                ldsm4(r, sb + (uint32_t)(((n0 + np * 16 + b_row) * LDS_PAD + kk + b_k) << 2));
                bfr[np * 2 + 0][0] = r[0]; bfr[np * 2 + 0][1] = r[1];
                bfr[np * 2 + 1][0] = r[2]; bfr[np * 2 + 1][1] = r[3];
            }
#pragma unroll
            for (int mt = 0; mt < MT; mt++)
#pragma unroll
                for (int nt = 0; nt < NT; nt++)
                    mma8(&acc[(mt * NT + nt) * 4], afr[mt], bfr[nt]);
        }
        __syncthreads();
    }
}

// ---------------- kernel 1: QKV = X @ W^T + b, scatter Q/K/V (rounded) ----------------
#define GEMM_SMEM_BYTES (2u * (128 + 128) * LDS_PAD * 4)

__global__ __launch_bounds__(256, 2)
void qkv_mma_kernel(const float* __restrict__ bias) {
    constexpr int BN = 128, WM = 2, WN = 4;
    constexpr int MT = 4, NT = 4;
    extern __shared__ float smp[];
    float* sA = smp;
    float* sB = smp + 2 * 128 * LDS_PAD;
    float acc[MT * NT * 4];
#pragma unroll
    for (int i = 0; i < MT * NT * 4; i++) acc[i] = 0.f;

    const int row0 = blockIdx.y * 128;
    const int col0 = blockIdx.x * 128;
    gemm_mainloop_async<BN, WM, WN>(g_Xr + (size_t)row0 * E_, E_,
                                    g_Wr + (size_t)col0 * E_, E_, E_, sA, sB, acc);

    const int tid = threadIdx.x;
    const int warp = tid >> 5, lane = tid & 31;
    const int wm = warp % WM, wn = warp / WM;

#pragma unroll
    for (int mt = 0; mt < MT; mt++) {
#pragma unroll
        for (int nt = 0; nt < NT; nt++) {
            const float* c = &acc[(mt * NT + nt) * 4];
            int n = col0 + wn * 32 + nt * 8 + 2 * (lane & 3);
            int h = n / 192;
            int rr = n - h * 192;
            int part = rr >> 6;
            int d = rr & 63;
            float* dst = (part == 0) ? g_Q : ((part == 1) ? g_K : g_V);
            float b0 = bias[n], b1 = bias[n + 1];
            float qs = (part == 0) ? 0.03125f : 1.f;   // fold 1/TEMP into Q (exact pow2)
#pragma unroll
            for (int half = 0; half < 2; half++) {
                int m = row0 + wm * 64 + mt * 16 + (lane >> 2) + half * 8;
                int bidx = m >> 10;
                int s = m & 1023;
                float2 v = make_float2(round_tf32f(c[half * 2 + 0] + b0) * qs,
                                       round_tf32f(c[half * 2 + 1] + b1) * qs);
                *reinterpret_cast<float2*>(
                    &dst[(((size_t)bidx * H_ + h) * S_ + s) * HD_ + d]) = v;
            }
        }
    }
}

// ---------------- V transpose ----------------
__global__ void vt_kernel() {
    __shared__ float t[32][33];
    int g = blockIdx.z;
    int s0 = blockIdx.y * 32, d0 = blockIdx.x * 32;
    const float* V = g_V + (size_t)g * S_ * HD_;
    float* Vt = g_Vt + (size_t)g * HD_ * S_;
    for (int i = threadIdx.y; i < 32; i += 8)
        t[i][threadIdx.x] = V[(size_t)(s0 + i) * HD_ + d0 + threadIdx.x];
    __syncthreads();
    for (int i = threadIdx.y; i < 32; i += 8)
        Vt[(size_t)(d0 + i) * S_ + s0 + threadIdx.x] = t[threadIdx.x][i];
}

// ---------------- flash attention, 64-row CTAs, cp.async tiles ----------------
// smem (floats): sQ[64*68]=4352 | sSK: K[128*68]=8704 / P[64*132]=8448 (aliased)
//                | sV[64*132]=8448 | sMax[64*4] | sSum[64*4]
#define FQ_OFF  0
#define FS_OFF  4352
#define FV_OFF  13056
#define FMX_OFF 21504
#define FSM_OFF 21760
#define FLASH_SMEM_BYTES (22016 * 4)

__global__ __launch_bounds__(256, 2)
void flash_kernel(const float* __restrict__ prev) {
    extern __shared__ float sm[];
    float* sMax = sm + FMX_OFF;
    float* sSum = sm + FSM_OFF;

    const int g = blockIdx.y;
    const int row0 = blockIdx.x * 64;
    const int tid = threadIdx.x, warp = tid >> 5, lane = tid & 31;
    const int wm = warp & 1, wn = warp >> 1;
    const int m0 = wm * 32;
    const int nS0 = wn * 32;
    const int nO0 = wn * 16;
    const int rowq = lane >> 2;
    const int coln2 = 2 * (lane & 3);

    const int a_row = (lane & 7) + ((lane & 8) ? 8 : 0);
    const int a_k   = (lane & 16) ? 4 : 0;
    const int b_row = (lane & 7) + ((lane & 16) ? 8 : 0);
    const int b_k   = (lane & 8) ? 4 : 0;

    const float* Qg  = g_Q  + (size_t)g * S_ * HD_ + (size_t)row0 * HD_;
    const float* Kg  = g_K  + (size_t)g * S_ * HD_;
    const float* Vtg = g_Vt + (size_t)g * HD_ * S_;

    const uint32_t sq_b = smem_u32(sm + FQ_OFF);
    const uint32_t ss_b = smem_u32(sm + FS_OFF);
    const uint32_t sv_b = smem_u32(sm + FV_OFF);

    // Q tile 64x64 via cp.async (pre-rounded, pre-scaled)
#pragma unroll
    for (int i = 0; i < 4; i++) {
        int f = tid + i * 256;
        int r = f >> 4, q = f & 15;
        cpa16(sq_b + (uint32_t)((r * 68 + (q << 2)) << 2), &Qg[(size_t)r * HD_ + (q << 2)]);
    }
    cpa_commit();

    float o_acc[2][2][4];
#pragma unroll
    for (int a = 0; a < 2; a++)
#pragma unroll
        for (int b = 0; b < 2; b++)
#pragma unroll
            for (int c = 0; c < 4; c++) o_acc[a][b][c] = 0.f;
    float m_i[2][2], l_i[2][2];
#pragma unroll
    for (int a = 0; a < 2; a++) { m_i[a][0] = m_i[a][1] = -1e30f; l_i[a][0] = l_i[a][1] = 0.f; }

    for (int cblk = 0; cblk < 8; cblk++) {
        const int col0 = cblk * 128;
        // issue K tile 128x64 + Vt tile 64x128 (raw copies)
#pragma unroll
        for (int i = 0; i < 8; i++) {
            int f = tid + i * 256;
            int r = f >> 4, q = f & 15;
            cpa16(ss_b + (uint32_t)((r * 68 + (q << 2)) << 2),
                  &Kg[(size_t)(col0 + r) * HD_ + (q << 2)]);
        }
#pragma unroll
        for (int i = 0; i < 8; i++) {
            int f = tid + i * 256;
            int r = f >> 5, q = f & 31;
            cpa16(sv_b + (uint32_t)((r * 132 + (q << 2)) << 2),
                  &Vtg[(size_t)r * S_ + col0 + (q << 2)]);
        }
        cpa_commit();

        // ---- acc init = prev + maskF (overlaps the cp.async transfers) ----
        float s_acc[2][4][4];
#pragma unroll
        for (int mt = 0; mt < 2; mt++) {
#pragma unroll
            for (int nt = 0; nt < 4; nt++) {
                int n = col0 + nS0 + nt * 8 + coln2;
#pragma unroll
                for (int half = 0; half < 2; half++) {
                    int m = row0 + m0 + mt * 16 + rowq + half * 8;
                    float2 pv = *reinterpret_cast<const float2*>(
                        &prev[((size_t)g * S_ + m) * S_ + n]);
                    float2 mf = *reinterpret_cast<const float2*>(
                        &g_maskF[(size_t)m * S_ + n]);
                    s_acc[mt][nt][half * 2 + 0] = pv.x + mf.x;
                    s_acc[mt][nt][half * 2 + 1] = pv.y + mf.y;
                }
            }
        }
        cpa_wait<0>();
        __syncthreads();

        // ---- S += (Q/32) @ K^T ----
#pragma unroll
        for (int ks = 0; ks < 8; ks++) {
            const int kk = ks << 3;
            uint32_t afr[2][4];
#pragma unroll
            for (int mt = 0; mt < 2; mt++)
                ldsm4(afr[mt], sq_b + (uint32_t)(((m0 + mt * 16 + a_row) * 68 + kk + a_k) << 2));
            uint32_t bfr[4][2];
#pragma unroll
            for (int np = 0; np < 2; np++) {
                uint32_t r[4];
                ldsm4(r, ss_b + (uint32_t)(((nS0 + np * 16 + b_row) * 68 + kk + b_k) << 2));
                bfr[np * 2 + 0][0] = r[0]; bfr[np * 2 + 0][1] = r[1];
                bfr[np * 2 + 1][0] = r[2]; bfr[np * 2 + 1][1] = r[3];
            }
#pragma unroll
            for (int mt = 0; mt < 2; mt++)
#pragma unroll
                for (int nt = 0; nt < 4; nt++)
                    mma8(s_acc[mt][nt], afr[mt], bfr[nt]);
        }

        // ---- row max ----
        float rmax[2][2];
#pragma unroll
        for (int mt = 0; mt < 2; mt++) { rmax[mt][0] = -1e30f; rmax[mt][1] = -1e30f; }
#pragma unroll
        for (int mt = 0; mt < 2; mt++) {
#pragma unroll
            for (int nt = 0; nt < 4; nt++)
#pragma unroll
                for (int half = 0; half < 2; half++)
                    rmax[mt][half] = fmaxf(rmax[mt][half],
                        fmaxf(s_acc[mt][nt][half * 2], s_acc[mt][nt][half * 2 + 1]));
#pragma unroll
            for (int half = 0; half < 2; half++) {
                float r = rmax[mt][half];
                r = fmaxf(r, __shfl_xor_sync(0xffffffffu, r, 1));
                r = fmaxf(r, __shfl_xor_sync(0xffffffffu, r, 2));
                if ((lane & 3) == 0)
                    sMax[(m0 + mt * 16 + rowq + half * 8) * 4 + wn] = r;
            }
        }
        __syncthreads();

        // ---- online rescale; p = exp(s - mnew) -> P smem; sums ----
        float mnew[2][2];
#pragma unroll
        for (int mt = 0; mt < 2; mt++) {
#pragma unroll
            for (int half = 0; half < 2; half++) {
                int rl = m0 + mt * 16 + rowq + half * 8;
                float mc = fmaxf(fmaxf(sMax[rl * 4 + 0], sMax[rl * 4 + 1]),
                                 fmaxf(sMax[rl * 4 + 2], sMax[rl * 4 + 3]));
                float mo = m_i[mt][half];
                float mn = fmaxf(mo, mc);
                float alpha = __expf(mo - mn);
                m_i[mt][half] = mn;
                mnew[mt][half] = mn;
                l_i[mt][half] *= alpha;
#pragma unroll
                for (int nt = 0; nt < 2; nt++) {
                    o_acc[mt][nt][half * 2 + 0] *= alpha;
                    o_acc[mt][nt][half * 2 + 1] *= alpha;
                }
            }
        }

        float* sP = sm + FS_OFF;
        float rsum[2][2];
#pragma unroll
        for (int mt = 0; mt < 2; mt++) { rsum[mt][0] = 0.f; rsum[mt][1] = 0.f; }
#pragma unroll
        for (int mt = 0; mt < 2; mt++) {
#pragma unroll
            for (int nt = 0; nt < 4; nt++) {
#pragma unroll
                for (int half = 0; half < 2; half++) {
                    float p0 = __expf(s_acc[mt][nt][half * 2 + 0] - mnew[mt][half]);
                    float p1 = __expf(s_acc[mt][nt][half * 2 + 1] - mnew[mt][half]);
                    rsum[mt][half] += p0 + p1;
                    uint2 u = make_uint2(cvt_tf32(p0), cvt_tf32(p1));
                    int rl = m0 + mt * 16 + rowq + half * 8;
                    *reinterpret_cast<uint2*>(
                        &sP[rl * 132 + nS0 + nt * 8 + coln2]) = u;
                }
            }
#pragma unroll
            for (int half = 0; half < 2; half++) {
                float r = rsum[mt][half];
                r += __shfl_xor_sync(0xffffffffu, r, 1);
                r += __shfl_xor_sync(0xffffffffu, r, 2);
                if ((lane & 3) == 0)
                    sSum[(m0 + mt * 16 + rowq + half * 8) * 4 + wn] = r;
            }
        }
        __syncthreads();

#pragma unroll
        for (int mt = 0; mt < 2; mt++)
#pragma unroll
            for (int half = 0; half < 2; half++) {
                int rl = m0 + mt * 16 + rowq + half * 8;
                l_i[mt][half] += sSum[rl * 4 + 0] + sSum[rl * 4 + 1]
                               + sSum[rl * 4 + 2] + sSum[rl * 4 + 3];
            }

        // ---- O += P @ Vt^T ----
#pragma unroll
        for (int ks = 0; ks < 16; ks++) {
            const int kk = ks << 3;
            uint32_t afr[2][4];
#pragma unroll
            for (int mt = 0; mt < 2; mt++)
                ldsm4(afr[mt], ss_b + (uint32_t)(((m0 + mt * 16 + a_row) * 132 + kk + a_k) << 2));
            uint32_t r[4];
            ldsm4(r, sv_b + (uint32_t)(((nO0 + b_row) * 132 + kk + b_k) << 2));
            uint32_t bfr[2][2];
            bfr[0][0] = r[0]; bfr[0][1] = r[1];
            bfr[1][0] = r[2]; bfr[1][1] = r[3];
#pragma unroll
            for (int mt = 0; mt < 2; mt++)
#pragma unroll
                for (int nt = 0; nt < 2; nt++)
                    mma8(o_acc[mt][nt], afr[mt], bfr[nt]);
        }
        __syncthreads();
    }

    // ---- epilogue: rounded O (ready for raw cp.async in out GEMM) ----
    const int bidx = g >> 4;
    const int h = g & 15;
#pragma unroll
    for (int mt = 0; mt < 2; mt++) {
#pragma unroll
        for (int half = 0; half < 2; half++) {
            float inv = 1.f / l_i[mt][half];
            int s = row0 + m0 + mt * 16 + rowq + half * 8;
#pragma unroll
            for (int nt = 0; nt < 2; nt++) {
                int d = nO0 + nt * 8 + coln2;
                float2 v = make_float2(round_tf32f(o_acc[mt][nt][half * 2 + 0] * inv),
                                       round_tf32f(o_acc[mt][nt][half * 2 + 1] * inv));
                *reinterpret_cast<float2*>(
                    &g_O[((size_t)bidx * S_ + s) * E_ + h * HD_ + d]) = v;
            }
        }
    }
}

// ---------------- kernel 4: out = O @ o_w^T + o_b ----------------
__global__ __launch_bounds__(256, 2)
void out_mma_kernel(const float* __restrict__ bias, float* __restrict__ out) {
    constexpr int BN = 128, WM = 2, WN = 4;
    constexpr int MT = 4, NT = 4;
    extern __shared__ float smp[];
    float* sA = smp;
    float* sB = smp + 2 * 128 * LDS_PAD;
    float acc[MT * NT * 4];
#pragma unroll
    for (int i = 0; i < MT * NT * 4; i++) acc[i] = 0.f;

    const int row0 = blockIdx.y * 128;
    const int col0 = blockIdx.x * 128;
    gemm_mainloop_async<BN, WM, WN>(g_O + (size_t)row0 * E_, E_,
                                    g_OWr + (size_t)col0 * E_, E_, E_, sA, sB, acc);

    const int tid = threadIdx.x;
    const int warp = tid >> 5, lane = tid & 31;
    const int wm = warp % WM, wn = warp / WM;

#pragma unroll
    for (int mt = 0; mt < MT; mt++) {
#pragma unroll
        for (int nt = 0; nt < NT; nt++) {
            const float* c = &acc[(mt * NT + nt) * 4];
            int n = col0 + wn * 32 + nt * 8 + 2 * (lane & 3);
            float b0 = bias[n], b1 = bias[n + 1];
#pragma unroll
            for (int half = 0; half < 2; half++) {
                int m = row0 + wm * 64 + mt * 16 + (lane >> 2) + half * 8;
                float2 v = make_float2(c[half * 2 + 0] + b0, c[half * 2 + 1] + b1);
                *reinterpret_cast<float2*>(&out[(size_t)m * E_ + n]) = v;
            }
        }
    }
}

// ---------------- launch ----------------
extern "C" void kernel_launch(void* const* d_in, const int* in_sizes, int n_in,
                              void* d_out, int out_size) {
    const float* x     = (const float*)d_in[0];
    const void*  mask  = d_in[1];
    const float* prev  = (const float*)d_in[2];
    const float* qkv_w = (const float*)d_in[3];
    const float* qkv_b = (const float*)d_in[4];
    const float* o_w   = (const float*)d_in[5];
    const float* o_b   = (const float*)d_in[6];
    float* out = (float*)d_out;

    cudaFuncSetAttribute(flash_kernel,
                         cudaFuncAttributeMaxDynamicSharedMemorySize, FLASH_SMEM_BYTES);
    cudaFuncSetAttribute(qkv_mma_kernel,
                         cudaFuncAttributeMaxDynamicSharedMemorySize, GEMM_SMEM_BYTES);
    cudaFuncSetAttribute(out_mma_kernel,
                         cudaFuncAttributeMaxDynamicSharedMemorySize, GEMM_SMEM_BYTES);

    detect_mask_kind_kernel<<<1, 32>>>((const unsigned int*)mask);
    mask_to_float_kernel<<<(S_ * S_) / 256, 256>>>(mask);

    // tf32 pre-round of GEMM operands (dst device globals resolved device-side)
    round4_kernel<<<(B_ * S_ * E_) / 1024, 256>>>((const float4*)x, 0);
    round4_kernel<<<(N3E * E_) / 1024, 256>>>((const float4*)qkv_w, 1);
    round4_kernel<<<(E_ * E_) / 1024, 256>>>((const float4*)o_w, 2);

    qkv_mma_kernel<<<dim3(N3E / 128, (B_ * S_) / 128), 256, GEMM_SMEM_BYTES>>>(qkv_b);

    vt_kernel<<<dim3(HD_ / 32, S_ / 32, B_ * H_), dim3(32, 8)>>>();

    flash_kernel<<<dim3(S_ / 64, B_ * H_), 256, FLASH_SMEM_BYTES>>>(prev);

    out_mma_kernel<<<dim3(E_ / 128, (B_ * S_) / 128), 256, GEMM_SMEM_BYTES>>>(o_b, out);
}